// round 9
// baseline (speedup 1.0000x reference)
#include <cuda_runtime.h>
#include <cuda_bf16.h>
#include <math.h>

#define NNODE   50000
#define NEDGE   800000
#define ETOT    (NEDGE + NNODE)
#define IN_DIM  256
#define FEAT    128
#define HEADS   4
#define NHID    32
#define NEG_SLOPE 0.2f
#define NPAD    50176

typedef unsigned long long u64;

// ---------------- device scratch (static, no allocation) ----------------
__device__ float g_bufA[NNODE * FEAT];   // h (fp32): GEMM out -> gather in
__device__ float g_bufB[NNODE * FEAT];   // gather1 out -> GEMM2 in
__device__ float g_as[NNODE * HEADS];
__device__ float g_ad[NNODE * HEADS];
__device__ int   g_deg[NPAD];
__device__ int   g_rs[NPAD];
__device__ int   g_bsum[256];
__device__ int   g_bsumX[256];
__device__ int   g_ssrc[ETOT];

__device__ __forceinline__ float lrelu(float x) { return x > 0.f ? x : NEG_SLOPE * x; }

__device__ __forceinline__ u64 pack2(float lo, float hi) {
    u64 r; asm("mov.b64 %0, {%1, %2};" : "=l"(r) : "f"(lo), "f"(hi)); return r;
}
__device__ __forceinline__ u64 fma2(u64 a, u64 b, u64 c) {
    u64 d; asm("fma.rn.f32x2 %0, %1, %2, %3;" : "=l"(d) : "l"(a), "l"(b), "l"(c)); return d;
}
__device__ __forceinline__ void unpack2(u64 p, float& lo, float& hi) {
    asm("mov.b64 {%0, %1}, %2;" : "=f"(lo), "=f"(hi) : "l"(p));
}

// ---------------- CSR build ----------------
// 4 edges per thread for MLP on the atomics
__global__ void hist_kernel(const int* __restrict__ ei, int E, int Etot,
                            int* __restrict__ deg) {
    int base = (blockIdx.x * blockDim.x + threadIdx.x) * 4;
#pragma unroll
    for (int j = 0; j < 4; j++) {
        int e = base + j;
        if (e < Etot) {
            int dst = (e < E) ? __ldg(&ei[E + e]) : (e - E);
            atomicAdd(&deg[dst], 1);
        }
    }
}

__global__ void scan_block_kernel(const int* __restrict__ in, int* __restrict__ out,
                                  int* __restrict__ bsum, int n) {
    __shared__ int wsum[8];
    int tid = threadIdx.x;
    int lane = tid & 31, w = tid >> 5;
    int i = blockIdx.x * 256 + tid;
    int v = (i < n) ? in[i] : 0;
    int x = v;
#pragma unroll
    for (int o = 1; o < 32; o <<= 1) {
        int t = __shfl_up_sync(0xFFFFFFFFu, x, o);
        if (lane >= o) x += t;
    }
    if (lane == 31) wsum[w] = x;
    __syncthreads();
    if (w == 0) {
        int s = (lane < 8) ? wsum[lane] : 0;
#pragma unroll
        for (int o = 1; o < 8; o <<= 1) {
            int t = __shfl_up_sync(0xFFFFFFFFu, s, o);
            if (lane >= o) s += t;
        }
        if (lane < 8) wsum[lane] = s;
    }
    __syncthreads();
    int woff = (w > 0) ? wsum[w - 1] : 0;
    if (i < n) out[i] = x + woff - v;          // exclusive (block-local)
    if (bsum && tid == 255) bsum[blockIdx.x] = wsum[7];
}

__global__ void scatter_kernel(const int* __restrict__ ei, int E, int Etot,
                               int* __restrict__ rs, const int* __restrict__ boff,
                               int* __restrict__ ssrc) {
    int base = (blockIdx.x * blockDim.x + threadIdx.x) * 4;
#pragma unroll
    for (int j = 0; j < 4; j++) {
        int e = base + j;
        if (e < Etot) {
            int src, dst;
            if (e < E) { src = __ldg(&ei[e]); dst = __ldg(&ei[E + e]); }
            else       { src = dst = e - E; }
            int pos = atomicAdd(&rs[dst], 1) + __ldg(&boff[dst >> 8]);
            ssrc[pos] = src;
        }
    }
}

// ---------------- f32x2 GEMM (128x128 block, 8x8/thread) + alpha epilogue -----
template <int K, int H>
__global__ void __launch_bounds__(256) gemm128_kernel(
    const float* __restrict__ A, const float* __restrict__ B,
    float* __restrict__ C, int M,
    const float* __restrict__ attS, const float* __restrict__ attD,
    float* __restrict__ as_, float* __restrict__ ad_)
{
    __shared__ float As[16][128];   // transposed: [k][row]
    __shared__ float Bs[16][128];   // [k][col]

    const int t  = threadIdx.x;
    const int tx = t & 15;
    const int ty = t >> 4;
    const int rowBase = blockIdx.x * 128;

    u64 acc2[8][4];
#pragma unroll
    for (int i = 0; i < 8; i++)
#pragma unroll
        for (int j = 0; j < 4; j++) acc2[i][j] = 0ull;

    const int ar = t >> 1;
    const int ac = (t & 1) * 8;
    const int br = t >> 4;
    const int bc = (t & 15) * 8;

    for (int k0 = 0; k0 < K; k0 += 16) {
        int grow = rowBase + ar;
        float4 a0, a1;
        if (grow < M) {
            a0 = *(const float4*)&A[(long)grow * K + k0 + ac];
            a1 = *(const float4*)&A[(long)grow * K + k0 + ac + 4];
        } else {
            a0 = make_float4(0.f, 0.f, 0.f, 0.f);
            a1 = a0;
        }
        As[ac + 0][ar] = a0.x; As[ac + 1][ar] = a0.y;
        As[ac + 2][ar] = a0.z; As[ac + 3][ar] = a0.w;
        As[ac + 4][ar] = a1.x; As[ac + 5][ar] = a1.y;
        As[ac + 6][ar] = a1.z; As[ac + 7][ar] = a1.w;
        *(float4*)&Bs[br][bc]     = *(const float4*)&B[(long)(k0 + br) * 128 + bc];
        *(float4*)&Bs[br][bc + 4] = *(const float4*)&B[(long)(k0 + br) * 128 + bc + 4];
        __syncthreads();

#pragma unroll
        for (int k = 0; k < 16; k++) {
            ulonglong2 bA = *(const ulonglong2*)&Bs[k][tx * 8];
            ulonglong2 bB = *(const ulonglong2*)&Bs[k][tx * 8 + 4];
            u64 bp0 = bA.x, bp1 = bA.y, bp2 = bB.x, bp3 = bB.y;
            float4 av0 = *(const float4*)&As[k][ty * 8];
            float4 av1 = *(const float4*)&As[k][ty * 8 + 4];
            float a8[8] = {av0.x, av0.y, av0.z, av0.w, av1.x, av1.y, av1.z, av1.w};
#pragma unroll
            for (int i = 0; i < 8; i++) {
                u64 ap = pack2(a8[i], a8[i]);
                acc2[i][0] = fma2(ap, bp0, acc2[i][0]);
                acc2[i][1] = fma2(ap, bp1, acc2[i][1]);
                acc2[i][2] = fma2(ap, bp2, acc2[i][2]);
                acc2[i][3] = fma2(ap, bp3, acc2[i][3]);
            }
        }
        __syncthreads();
    }

    float4 s0 = *(const float4*)&attS[tx * 8];
    float4 s1 = *(const float4*)&attS[tx * 8 + 4];
    float4 d0 = *(const float4*)&attD[tx * 8];
    float4 d1 = *(const float4*)&attD[tx * 8 + 4];

#pragma unroll
    for (int i = 0; i < 8; i++) {
        int r = rowBase + ty * 8 + i;
        float c[8];
#pragma unroll
        for (int j = 0; j < 4; j++) unpack2(acc2[i][j], c[2 * j], c[2 * j + 1]);

        float ss = c[0]*s0.x + c[1]*s0.y + c[2]*s0.z + c[3]*s0.w
                 + c[4]*s1.x + c[5]*s1.y + c[6]*s1.z + c[7]*s1.w;
        float sd = c[0]*d0.x + c[1]*d0.y + c[2]*d0.z + c[3]*d0.w
                 + c[4]*d1.x + c[5]*d1.y + c[6]*d1.z + c[7]*d1.w;
        const int RED = (H == 4) ? 4 : 16;
#pragma unroll
        for (int o = 1; o < RED; o <<= 1) {
            ss += __shfl_xor_sync(0xFFFFFFFFu, ss, o);
            sd += __shfl_xor_sync(0xFFFFFFFFu, sd, o);
        }
        if (r < M) {
            *(float4*)&C[(long)r * 128 + tx * 8]     = make_float4(c[0], c[1], c[2], c[3]);
            *(float4*)&C[(long)r * 128 + tx * 8 + 4] = make_float4(c[4], c[5], c[6], c[7]);
            if ((tx & (RED - 1)) == 0) {
                int head = (H == 4) ? (tx >> 2) : 0;
                as_[r * H + head] = ss;
                ad_[r * H + head] = sd;
            }
        }
    }
}

// ---------------- fused gather: software-pipelined unroll-8 -------------------
// warp per dst node; lane -> channels [lane*4, lane*4+4)
template <int H, int DO_ELU>
__global__ void __launch_bounds__(256) gat_gather_kernel(
    const int* __restrict__ rs, const int* __restrict__ deg,
    const int* __restrict__ boff, const int* __restrict__ ssrc,
    const float* __restrict__ as_, const float* __restrict__ ad_,
    const float* __restrict__ h, const float* __restrict__ bias,
    float* __restrict__ out, int n)
{
    int g = blockIdx.x * blockDim.x + threadIdx.x;
    int node = g >> 5, lane = g & 31;
    if (node >= n) return;
    const int head = (H == 4) ? (lane >> 3) : 0;

    int d     = __ldg(&deg[node]);
    int start = __ldg(&rs[node]) + __ldg(&boff[node >> 8]) - d;  // rs holds end-local
    float adv = __ldg(&ad_[node * H + head]);

    float4 acc = make_float4(0.f, 0.f, 0.f, 0.f);
    float s = 0.f;

    int i = 0;
    for (; i + 8 <= d; i += 8) {
        int idx[8];
#pragma unroll
        for (int j = 0; j < 8; j++) idx[j] = __ldg(&ssrc[start + i + j]);
        float aw[8];
#pragma unroll
        for (int j = 0; j < 8; j++) aw[j] = __ldg(&as_[idx[j] * H + head]);
        float4 v[8];
#pragma unroll
        for (int j = 0; j < 8; j++) v[j] = *(const float4*)&h[(long)idx[j] * FEAT + lane * 4];
        float w[8];
#pragma unroll
        for (int j = 0; j < 8; j++) w[j] = __expf(lrelu(aw[j] + adv));
#pragma unroll
        for (int j = 0; j < 8; j++) {
            s += w[j];
            acc.x = fmaf(v[j].x, w[j], acc.x);
            acc.y = fmaf(v[j].y, w[j], acc.y);
            acc.z = fmaf(v[j].z, w[j], acc.z);
            acc.w = fmaf(v[j].w, w[j], acc.w);
        }
    }
    if (i + 4 <= d) {
        int idx[4];
#pragma unroll
        for (int j = 0; j < 4; j++) idx[j] = __ldg(&ssrc[start + i + j]);
        float aw[4];
#pragma unroll
        for (int j = 0; j < 4; j++) aw[j] = __ldg(&as_[idx[j] * H + head]);
        float4 v[4];
#pragma unroll
        for (int j = 0; j < 4; j++) v[j] = *(const float4*)&h[(long)idx[j] * FEAT + lane * 4];
#pragma unroll
        for (int j = 0; j < 4; j++) {
            float w = __expf(lrelu(aw[j] + adv));
            s += w;
            acc.x = fmaf(v[j].x, w, acc.x);
            acc.y = fmaf(v[j].y, w, acc.y);
            acc.z = fmaf(v[j].z, w, acc.z);
            acc.w = fmaf(v[j].w, w, acc.w);
        }
        i += 4;
    }
    for (; i < d; i++) {
        int s0i = __ldg(&ssrc[start + i]);
        float w = __expf(lrelu(__ldg(&as_[s0i * H + head]) + adv));
        float4 v = *(const float4*)&h[(long)s0i * FEAT + lane * 4];
        s += w;
        acc.x = fmaf(v.x, w, acc.x);
        acc.y = fmaf(v.y, w, acc.y);
        acc.z = fmaf(v.z, w, acc.z);
        acc.w = fmaf(v.w, w, acc.w);
    }

    float inv = 1.0f / (s + 1e-16f);
    float4 b4 = *(const float4*)&bias[lane * 4];
    float4 o;
    o.x = acc.x * inv + b4.x;
    o.y = acc.y * inv + b4.y;
    o.z = acc.z * inv + b4.z;
    o.w = acc.w * inv + b4.w;
    if (DO_ELU) {
        o.x = o.x > 0.f ? o.x : expm1f(o.x);
        o.y = o.y > 0.f ? o.y : expm1f(o.y);
        o.z = o.z > 0.f ? o.z : expm1f(o.z);
        o.w = o.w > 0.f ? o.w : expm1f(o.w);
    }
    *(float4*)&out[(long)node * FEAT + lane * 4] = o;
}

// =============================================================================
extern "C" void kernel_launch(void* const* d_in, const int* in_sizes, int n_in,
                              void* d_out, int out_size)
{
    const float* x        = (const float*)d_in[0];
    const int*   ei       = (const int*)  d_in[1];
    const float* W1       = (const float*)d_in[2];
    const float* att_src1 = (const float*)d_in[3];
    const float* att_dst1 = (const float*)d_in[4];
    const float* b1       = (const float*)d_in[5];
    const float* W2       = (const float*)d_in[6];
    const float* att_src2 = (const float*)d_in[7];
    const float* att_dst2 = (const float*)d_in[8];
    const float* b2       = (const float*)d_in[9];
    float* out = (float*)d_out;

    const int N    = in_sizes[0] / IN_DIM;   // 50000
    const int E    = in_sizes[1] / 2;        // 800000
    const int Etot = E + N;                  // 850000

    float *bufA, *bufB, *as_, *ad_;
    int *deg, *rs, *bsum, *bsumX, *ssrc;
    cudaGetSymbolAddress((void**)&bufA,  g_bufA);
    cudaGetSymbolAddress((void**)&bufB,  g_bufB);
    cudaGetSymbolAddress((void**)&as_,   g_as);
    cudaGetSymbolAddress((void**)&ad_,   g_ad);
    cudaGetSymbolAddress((void**)&deg,   g_deg);
    cudaGetSymbolAddress((void**)&rs,    g_rs);
    cudaGetSymbolAddress((void**)&bsum,  g_bsum);
    cudaGetSymbolAddress((void**)&bsumX, g_bsumX);
    cudaGetSymbolAddress((void**)&ssrc,  g_ssrc);

    const int nBlocks256 = (N + 255) / 256;          // 196
    const int eBlocks4   = (Etot + 1023) / 1024;     // 4 edges/thread
    const int warpBlocks = (N * 32 + 255) / 256;

    // ---- CSR build ----
    cudaMemsetAsync(deg, 0, (size_t)N * sizeof(int));
    hist_kernel<<<eBlocks4, 256>>>(ei, E, Etot, deg);
    scan_block_kernel<<<nBlocks256, 256>>>(deg, rs, bsum, N);
    scan_block_kernel<<<1, 256>>>(bsum, bsumX, (int*)nullptr, nBlocks256);
    scatter_kernel<<<eBlocks4, 256>>>(ei, E, Etot, rs, bsumX, ssrc);

    // ---- Layer 1 ----
    gemm128_kernel<IN_DIM, 4><<<(N + 127) / 128, 256>>>(x, W1, bufA, N,
                                                        att_src1, att_dst1, as_, ad_);
    gat_gather_kernel<4, 1><<<warpBlocks, 256>>>(rs, deg, bsumX, ssrc, as_, ad_,
                                                 bufA, b1, bufB, N);

    // ---- Layer 2 ----
    gemm128_kernel<FEAT, 1><<<(N + 127) / 128, 256>>>(bufB, W2, bufA, N,
                                                      att_src2, att_dst2, as_, ad_);
    gat_gather_kernel<1, 0><<<warpBlocks, 256>>>(rs, deg, bsumX, ssrc, as_, ad_,
                                                 bufA, b2, out, N);
}

// round 10
// speedup vs baseline: 1.0507x; 1.0507x over previous
#include <cuda_runtime.h>
#include <cuda_bf16.h>
#include <math.h>

#define NNODE   50000
#define NEDGE   800000
#define ETOT    (NEDGE + NNODE)
#define IN_DIM  256
#define FEAT    128
#define HEADS   4
#define NHID    32
#define NEG_SLOPE 0.2f
#define NPAD    50176

typedef unsigned long long u64;

// ---------------- device scratch (static, no allocation) ----------------
__device__ float g_bufA[NNODE * FEAT];   // h (fp32): GEMM out -> gather in
__device__ float g_bufB[NNODE * FEAT];   // gather1 out -> GEMM2 in
__device__ float g_as[NNODE * HEADS];
__device__ float g_ad[NNODE * HEADS];
__device__ int   g_deg[NPAD];
__device__ int   g_rs[NPAD];
__device__ int   g_bsum[256];
__device__ int   g_bsumX[256];
__device__ int   g_ssrc[ETOT];

__device__ __forceinline__ float lrelu(float x) { return x > 0.f ? x : NEG_SLOPE * x; }

__device__ __forceinline__ u64 pack2(float lo, float hi) {
    u64 r; asm("mov.b64 %0, {%1, %2};" : "=l"(r) : "f"(lo), "f"(hi)); return r;
}
__device__ __forceinline__ u64 fma2(u64 a, u64 b, u64 c) {
    u64 d; asm("fma.rn.f32x2 %0, %1, %2, %3;" : "=l"(d) : "l"(a), "l"(b), "l"(c)); return d;
}
__device__ __forceinline__ void unpack2(u64 p, float& lo, float& hi) {
    asm("mov.b64 {%0, %1}, %2;" : "=f"(lo), "=f"(hi) : "l"(p));
}

// ---------------- CSR build ----------------
__global__ void hist_kernel(const int* __restrict__ ei, int E, int Etot,
                            int* __restrict__ deg) {
    int e = blockIdx.x * blockDim.x + threadIdx.x;
    if (e >= Etot) return;
    int dst = (e < E) ? __ldg(&ei[E + e]) : (e - E);
    atomicAdd(&deg[dst], 1);
}

__global__ void scan_block_kernel(const int* __restrict__ in, int* __restrict__ out,
                                  int* __restrict__ bsum, int n) {
    __shared__ int wsum[8];
    int tid = threadIdx.x;
    int lane = tid & 31, w = tid >> 5;
    int i = blockIdx.x * 256 + tid;
    int v = (i < n) ? in[i] : 0;
    int x = v;
#pragma unroll
    for (int o = 1; o < 32; o <<= 1) {
        int t = __shfl_up_sync(0xFFFFFFFFu, x, o);
        if (lane >= o) x += t;
    }
    if (lane == 31) wsum[w] = x;
    __syncthreads();
    if (w == 0) {
        int s = (lane < 8) ? wsum[lane] : 0;
#pragma unroll
        for (int o = 1; o < 8; o <<= 1) {
            int t = __shfl_up_sync(0xFFFFFFFFu, s, o);
            if (lane >= o) s += t;
        }
        if (lane < 8) wsum[lane] = s;
    }
    __syncthreads();
    int woff = (w > 0) ? wsum[w - 1] : 0;
    if (i < n) out[i] = x + woff - v;          // exclusive (block-local)
    if (bsum && tid == 255) bsum[blockIdx.x] = wsum[7];
}

__global__ void scatter_kernel(const int* __restrict__ ei, int E, int Etot,
                               int* __restrict__ rs, const int* __restrict__ boff,
                               int* __restrict__ ssrc) {
    int e = blockIdx.x * blockDim.x + threadIdx.x;
    if (e >= Etot) return;
    int src, dst;
    if (e < E) { src = __ldg(&ei[e]); dst = __ldg(&ei[E + e]); }
    else       { src = dst = e - E; }
    int pos = atomicAdd(&rs[dst], 1) + __ldg(&boff[dst >> 8]);
    ssrc[pos] = src;
}

// ---------------- f32x2 GEMM (128x128 block, 8x8/thread) + alpha epilogue -----
template <int K, int H>
__global__ void __launch_bounds__(256) gemm128_kernel(
    const float* __restrict__ A, const float* __restrict__ B,
    float* __restrict__ C, int M,
    const float* __restrict__ attS, const float* __restrict__ attD,
    float* __restrict__ as_, float* __restrict__ ad_)
{
    __shared__ float As[16][128];   // transposed: [k][row]
    __shared__ float Bs[16][128];   // [k][col]

    const int t  = threadIdx.x;
    const int tx = t & 15;
    const int ty = t >> 4;
    const int rowBase = blockIdx.x * 128;

    u64 acc2[8][4];
#pragma unroll
    for (int i = 0; i < 8; i++)
#pragma unroll
        for (int j = 0; j < 4; j++) acc2[i][j] = 0ull;

    const int ar = t >> 1;
    const int ac = (t & 1) * 8;
    const int br = t >> 4;
    const int bc = (t & 15) * 8;

    for (int k0 = 0; k0 < K; k0 += 16) {
        int grow = rowBase + ar;
        float4 a0, a1;
        if (grow < M) {
            a0 = *(const float4*)&A[(long)grow * K + k0 + ac];
            a1 = *(const float4*)&A[(long)grow * K + k0 + ac + 4];
        } else {
            a0 = make_float4(0.f, 0.f, 0.f, 0.f);
            a1 = a0;
        }
        As[ac + 0][ar] = a0.x; As[ac + 1][ar] = a0.y;
        As[ac + 2][ar] = a0.z; As[ac + 3][ar] = a0.w;
        As[ac + 4][ar] = a1.x; As[ac + 5][ar] = a1.y;
        As[ac + 6][ar] = a1.z; As[ac + 7][ar] = a1.w;
        *(float4*)&Bs[br][bc]     = *(const float4*)&B[(long)(k0 + br) * 128 + bc];
        *(float4*)&Bs[br][bc + 4] = *(const float4*)&B[(long)(k0 + br) * 128 + bc + 4];
        __syncthreads();

#pragma unroll
        for (int k = 0; k < 16; k++) {
            ulonglong2 bA = *(const ulonglong2*)&Bs[k][tx * 8];
            ulonglong2 bB = *(const ulonglong2*)&Bs[k][tx * 8 + 4];
            u64 bp0 = bA.x, bp1 = bA.y, bp2 = bB.x, bp3 = bB.y;
            float4 av0 = *(const float4*)&As[k][ty * 8];
            float4 av1 = *(const float4*)&As[k][ty * 8 + 4];
            float a8[8] = {av0.x, av0.y, av0.z, av0.w, av1.x, av1.y, av1.z, av1.w};
#pragma unroll
            for (int i = 0; i < 8; i++) {
                u64 ap = pack2(a8[i], a8[i]);
                acc2[i][0] = fma2(ap, bp0, acc2[i][0]);
                acc2[i][1] = fma2(ap, bp1, acc2[i][1]);
                acc2[i][2] = fma2(ap, bp2, acc2[i][2]);
                acc2[i][3] = fma2(ap, bp3, acc2[i][3]);
            }
        }
        __syncthreads();
    }

    float4 s0 = *(const float4*)&attS[tx * 8];
    float4 s1 = *(const float4*)&attS[tx * 8 + 4];
    float4 d0 = *(const float4*)&attD[tx * 8];
    float4 d1 = *(const float4*)&attD[tx * 8 + 4];

#pragma unroll
    for (int i = 0; i < 8; i++) {
        int r = rowBase + ty * 8 + i;
        float c[8];
#pragma unroll
        for (int j = 0; j < 4; j++) unpack2(acc2[i][j], c[2 * j], c[2 * j + 1]);

        float ss = c[0]*s0.x + c[1]*s0.y + c[2]*s0.z + c[3]*s0.w
                 + c[4]*s1.x + c[5]*s1.y + c[6]*s1.z + c[7]*s1.w;
        float sd = c[0]*d0.x + c[1]*d0.y + c[2]*d0.z + c[3]*d0.w
                 + c[4]*d1.x + c[5]*d1.y + c[6]*d1.z + c[7]*d1.w;
        const int RED = (H == 4) ? 4 : 16;
#pragma unroll
        for (int o = 1; o < RED; o <<= 1) {
            ss += __shfl_xor_sync(0xFFFFFFFFu, ss, o);
            sd += __shfl_xor_sync(0xFFFFFFFFu, sd, o);
        }
        if (r < M) {
            *(float4*)&C[(long)r * 128 + tx * 8]     = make_float4(c[0], c[1], c[2], c[3]);
            *(float4*)&C[(long)r * 128 + tx * 8 + 4] = make_float4(c[4], c[5], c[6], c[7]);
            if ((tx & (RED - 1)) == 0) {
                int head = (H == 4) ? (tx >> 2) : 0;
                as_[r * H + head] = ss;
                ad_[r * H + head] = sd;
            }
        }
    }
}

// ---------------- fused gather: agg + normalize + bias (+ELU), unroll-4 -------
template <int H, int DO_ELU>
__global__ void __launch_bounds__(256) gat_gather_kernel(
    const int* __restrict__ rs, const int* __restrict__ deg,
    const int* __restrict__ boff, const int* __restrict__ ssrc,
    const float* __restrict__ as_, const float* __restrict__ ad_,
    const float* __restrict__ h, const float* __restrict__ bias,
    float* __restrict__ out, int n)
{
    int g = blockIdx.x * blockDim.x + threadIdx.x;
    int node = g >> 5, lane = g & 31;
    if (node >= n) return;
    const int head = (H == 4) ? (lane >> 3) : 0;

    int d     = __ldg(&deg[node]);
    int start = __ldg(&rs[node]) + __ldg(&boff[node >> 8]) - d;  // rs holds end-local
    float adv = __ldg(&ad_[node * H + head]);

    float4 acc = make_float4(0.f, 0.f, 0.f, 0.f);
    float s = 0.f;

    int i = 0;
    for (; i + 4 <= d; i += 4) {
        int i0 = __ldg(&ssrc[start + i]);
        int i1 = __ldg(&ssrc[start + i + 1]);
        int i2 = __ldg(&ssrc[start + i + 2]);
        int i3 = __ldg(&ssrc[start + i + 3]);
        float w0 = __expf(lrelu(__ldg(&as_[i0 * H + head]) + adv));
        float w1 = __expf(lrelu(__ldg(&as_[i1 * H + head]) + adv));
        float w2 = __expf(lrelu(__ldg(&as_[i2 * H + head]) + adv));
        float w3 = __expf(lrelu(__ldg(&as_[i3 * H + head]) + adv));
        float4 v0 = *(const float4*)&h[(long)i0 * FEAT + lane * 4];
        float4 v1 = *(const float4*)&h[(long)i1 * FEAT + lane * 4];
        float4 v2 = *(const float4*)&h[(long)i2 * FEAT + lane * 4];
        float4 v3 = *(const float4*)&h[(long)i3 * FEAT + lane * 4];
        s += (w0 + w1) + (w2 + w3);
        acc.x = fmaf(v0.x, w0, fmaf(v1.x, w1, fmaf(v2.x, w2, fmaf(v3.x, w3, acc.x))));
        acc.y = fmaf(v0.y, w0, fmaf(v1.y, w1, fmaf(v2.y, w2, fmaf(v3.y, w3, acc.y))));
        acc.z = fmaf(v0.z, w0, fmaf(v1.z, w1, fmaf(v2.z, w2, fmaf(v3.z, w3, acc.z))));
        acc.w = fmaf(v0.w, w0, fmaf(v1.w, w1, fmaf(v2.w, w2, fmaf(v3.w, w3, acc.w))));
    }
    for (; i < d; i++) {
        int s0i = __ldg(&ssrc[start + i]);
        float w = __expf(lrelu(__ldg(&as_[s0i * H + head]) + adv));
        float4 v = *(const float4*)&h[(long)s0i * FEAT + lane * 4];
        s += w;
        acc.x = fmaf(v.x, w, acc.x);
        acc.y = fmaf(v.y, w, acc.y);
        acc.z = fmaf(v.z, w, acc.z);
        acc.w = fmaf(v.w, w, acc.w);
    }

    float inv = 1.0f / (s + 1e-16f);
    float4 b4 = *(const float4*)&bias[lane * 4];
    float4 o;
    o.x = acc.x * inv + b4.x;
    o.y = acc.y * inv + b4.y;
    o.z = acc.z * inv + b4.z;
    o.w = acc.w * inv + b4.w;
    if (DO_ELU) {
        o.x = o.x > 0.f ? o.x : expm1f(o.x);
        o.y = o.y > 0.f ? o.y : expm1f(o.y);
        o.z = o.z > 0.f ? o.z : expm1f(o.z);
        o.w = o.w > 0.f ? o.w : expm1f(o.w);
    }
    *(float4*)&out[(long)node * FEAT + lane * 4] = o;
}

// =============================================================================
extern "C" void kernel_launch(void* const* d_in, const int* in_sizes, int n_in,
                              void* d_out, int out_size)
{
    const float* x        = (const float*)d_in[0];
    const int*   ei       = (const int*)  d_in[1];
    const float* W1       = (const float*)d_in[2];
    const float* att_src1 = (const float*)d_in[3];
    const float* att_dst1 = (const float*)d_in[4];
    const float* b1       = (const float*)d_in[5];
    const float* W2       = (const float*)d_in[6];
    const float* att_src2 = (const float*)d_in[7];
    const float* att_dst2 = (const float*)d_in[8];
    const float* b2       = (const float*)d_in[9];
    float* out = (float*)d_out;

    const int N    = in_sizes[0] / IN_DIM;   // 50000
    const int E    = in_sizes[1] / 2;        // 800000
    const int Etot = E + N;                  // 850000

    float *bufA, *bufB, *as_, *ad_;
    int *deg, *rs, *bsum, *bsumX, *ssrc;
    cudaGetSymbolAddress((void**)&bufA,  g_bufA);
    cudaGetSymbolAddress((void**)&bufB,  g_bufB);
    cudaGetSymbolAddress((void**)&as_,   g_as);
    cudaGetSymbolAddress((void**)&ad_,   g_ad);
    cudaGetSymbolAddress((void**)&deg,   g_deg);
    cudaGetSymbolAddress((void**)&rs,    g_rs);
    cudaGetSymbolAddress((void**)&bsum,  g_bsum);
    cudaGetSymbolAddress((void**)&bsumX, g_bsumX);
    cudaGetSymbolAddress((void**)&ssrc,  g_ssrc);

    const int nBlocks256 = (N + 255) / 256;          // 196
    const int eBlocks    = (Etot + 255) / 256;
    const int warpBlocks = (N * 32 + 255) / 256;

    // One side stream + fork/join events (created once; host-side only,
    // no device memory allocation).
    static cudaStream_t s2 = nullptr;
    static cudaEvent_t evFork = nullptr, evJoin = nullptr;
    if (!s2) {
        cudaStreamCreateWithFlags(&s2, cudaStreamNonBlocking);
        cudaEventCreateWithFlags(&evFork, cudaEventDisableTiming);
        cudaEventCreateWithFlags(&evJoin, cudaEventDisableTiming);
    }

    // ---- Fork: CSR build on s2, GEMM1 on main stream (independent) ----
    cudaEventRecord(evFork, 0);
    cudaStreamWaitEvent(s2, evFork, 0);

    cudaMemsetAsync(deg, 0, (size_t)N * sizeof(int), s2);
    hist_kernel<<<eBlocks, 256, 0, s2>>>(ei, E, Etot, deg);
    scan_block_kernel<<<nBlocks256, 256, 0, s2>>>(deg, rs, bsum, N);
    scan_block_kernel<<<1, 256, 0, s2>>>(bsum, bsumX, (int*)nullptr, nBlocks256);
    scatter_kernel<<<eBlocks, 256, 0, s2>>>(ei, E, Etot, rs, bsumX, ssrc);
    cudaEventRecord(evJoin, s2);

    gemm128_kernel<IN_DIM, 4><<<(N + 127) / 128, 256>>>(x, W1, bufA, N,
                                                        att_src1, att_dst1, as_, ad_);

    // ---- Join: gather1 needs both CSR and GEMM1 ----
    cudaStreamWaitEvent(0, evJoin, 0);
    gat_gather_kernel<4, 1><<<warpBlocks, 256>>>(rs, deg, bsumX, ssrc, as_, ad_,
                                                 bufA, b1, bufB, N);

    // ---- Layer 2 ----
    gemm128_kernel<FEAT, 1><<<(N + 127) / 128, 256>>>(bufB, W2, bufA, N,
                                                      att_src2, att_dst2, as_, ad_);
    gat_gather_kernel<1, 0><<<warpBlocks, 256>>>(rs, deg, bsumX, ssrc, as_, ad_,
                                                 bufA, b2, out, N);
}